// round 11
// baseline (speedup 1.0000x reference)
#include <cuda_runtime.h>

#define HW 4096  // 64*64
typedef unsigned long long ull;

// Device scratch
__device__ float g_act[4 * 64 * HW];      // [b][co=64][h][w]
__device__ float g_mask[4 * HW * 100];    // [b][pixel][k=25][s=4], softmaxed
__device__ float g_wt2[576 * 112];        // enc w: [t=ci*9+r][s=4][28pad]
__device__ float g_wct[256 * 64];         // comp w: [c][o]

// ---- f32x2 helpers -------------------------------------------------------
__device__ __forceinline__ void ffma2(ull& d, ull a, ull b) {
  asm("fma.rn.f32x2 %0, %1, %2, %0;" : "+l"(d) : "l"(a), "l"(b));
}
__device__ __forceinline__ ull addf32x2(ull a, ull b) {
  ull d;
  asm("add.rn.f32x2 %0, %1, %2;" : "=l"(d) : "l"(a), "l"(b));
  return d;
}
__device__ __forceinline__ ull dup2(float v) {
  ull d;
  asm("mov.b64 %0, {%1, %1};" : "=l"(d) : "r"(__float_as_uint(v)));
  return d;
}
__device__ __forceinline__ float lo32(ull d) { return __uint_as_float((unsigned)d); }
__device__ __forceinline__ float hi32(ull d) { return __uint_as_float((unsigned)(d >> 32)); }

// ---------------------------------------------------------------------------
// kW: one-time weight reorganization
// ---------------------------------------------------------------------------
__global__ void __launch_bounds__(256) kW(const float* __restrict__ wc,
                                          const float* __restrict__ we) {
  int idx = blockIdx.x * 256 + threadIdx.x;
  if (idx < 576 * 112) {
    int t = idx / 112;
    int rem = idx - t * 112;
    int s = rem / 28, k = rem - s * 28;
    g_wt2[idx] = (k < 25) ? we[(k * 4 + s) * 576 + t] : 0.f;
  }
  int j = idx - 576 * 112;
  if (j >= 0 && j < 256 * 64) {
    int c = j >> 6, o = j & 63;
    g_wct[j] = wc[o * 256 + c];
  }
}

// ---------------------------------------------------------------------------
// kA: 1x1 conv (256->64) + BN + SiLU, f32x2 over output pairs.
// 256 threads/block (8 warps) -> 13.8 warps/SM at grid 256.
// Thread tile: 4 px x 4 outputs (2 o-pairs).
// ---------------------------------------------------------------------------
__global__ void __launch_bounds__(256) kA(
    const float* __restrict__ x,
    const float* __restrict__ gma, const float* __restrict__ bet,
    const float* __restrict__ mea, const float* __restrict__ var) {
  __shared__ float xs[64 * 64];
  __shared__ float ws[64 * 64];

  int blk = blockIdx.x;
  int b = blk >> 6;
  int p0 = (blk & 63) << 6;
  int tid = threadIdx.x;
  int pp = tid & 15;   // 4 pixels
  int po = tid >> 4;   // 0..15 -> 4 outputs (2 pairs)

  ull acc[2][4];
#pragma unroll
  for (int a = 0; a < 2; a++)
#pragma unroll
    for (int p = 0; p < 4; p++) acc[a][p] = 0ull;

  const float* xb = x + (size_t)(b * 256) * HW + p0;

#pragma unroll 1
  for (int cc = 0; cc < 4; cc++) {
    __syncthreads();
    const float4* xg = (const float4*)(xb + (size_t)cc * 64 * HW);
    float4* xsd = (float4*)xs;
    for (int u = tid; u < 1024; u += 256) {
      int ci = u >> 4, m = u & 15;
      xsd[u] = xg[ci * 1024 + m];
    }
    const float4* wg = (const float4*)(g_wct + cc * 64 * 64);
    float4* wsd = (float4*)ws;
    for (int u = tid; u < 1024; u += 256) wsd[u] = wg[u];
    __syncthreads();

#pragma unroll 4
    for (int ci = 0; ci < 64; ci++) {
      float4 xv = *(const float4*)(xs + ci * 64 + pp * 4);
      ull xd[4] = {dup2(xv.x), dup2(xv.y), dup2(xv.z), dup2(xv.w)};
      const ull* wp = (const ull*)(ws + ci * 64 + po * 4);
      ull w0 = wp[0], w1 = wp[1];
#pragma unroll
      for (int p = 0; p < 4; p++) {
        ffma2(acc[0][p], w0, xd[p]);
        ffma2(acc[1][p], w1, xd[p]);
      }
    }
  }

  float* actb = g_act + (size_t)(b * 64) * HW + p0 + pp * 4;
#pragma unroll
  for (int op = 0; op < 2; op++) {
    int o = po * 4 + op * 2;
    float inv0 = gma[o] * rsqrtf(var[o] + 1e-5f);
    float off0 = bet[o] - mea[o] * inv0;
    float inv1 = gma[o + 1] * rsqrtf(var[o + 1] + 1e-5f);
    float off1 = bet[o + 1] - mea[o + 1] * inv1;
    float4 r0, r1;
    float v;
    v = lo32(acc[op][0]) * inv0 + off0; r0.x = v / (1.f + __expf(-v));
    v = lo32(acc[op][1]) * inv0 + off0; r0.y = v / (1.f + __expf(-v));
    v = lo32(acc[op][2]) * inv0 + off0; r0.z = v / (1.f + __expf(-v));
    v = lo32(acc[op][3]) * inv0 + off0; r0.w = v / (1.f + __expf(-v));
    v = hi32(acc[op][0]) * inv1 + off1; r1.x = v / (1.f + __expf(-v));
    v = hi32(acc[op][1]) * inv1 + off1; r1.y = v / (1.f + __expf(-v));
    v = hi32(acc[op][2]) * inv1 + off1; r1.z = v / (1.f + __expf(-v));
    v = hi32(acc[op][3]) * inv1 + off1; r1.w = v / (1.f + __expf(-v));
    *(float4*)(actb + (size_t)o * HW) = r0;
    *(float4*)(actb + (size_t)(o + 1) * HW) = r1;
  }
}

// ---------------------------------------------------------------------------
// kB: 3x3 conv (64->100ch) + softmax over k. f32x2 over adjacent k.
// 256 threads/block, 1 pixel/thread (64 px-slots x 4 s) -> 13.8 warps/SM.
// ---------------------------------------------------------------------------
__global__ void __launch_bounds__(256, 2) kB() {
  __shared__ float as_[6400];   // act tile [64][10][10]
  __shared__ float ws[4032];    // weight chunk [36][112]

  int b = blockIdx.z;
  int i0 = blockIdx.y << 3, j0 = blockIdx.x << 3;
  int tid = threadIdx.x;
  int s = tid & 3, q = tid >> 2;   // q 0..63
  int ty = q >> 3, tx = q & 7;

  for (int idx = tid; idx < 6400; idx += 256) {
    int ci = idx / 100;
    int rem = idx - ci * 100;
    int rr = rem / 10, cc2 = rem - rr * 10;
    int gi = i0 + rr - 1, gj = j0 + cc2 - 1;
    float v = 0.f;
    if ((unsigned)gi < 64u && (unsigned)gj < 64u)
      v = g_act[((size_t)(b * 64 + ci)) * HW + (gi << 6) + gj];
    as_[idx] = v;
  }

  ull ap_[12];
  float at = 0.f;
#pragma unroll
  for (int t = 0; t < 12; t++) ap_[t] = 0ull;

#pragma unroll 1
  for (int cc = 0; cc < 16; cc++) {
    __syncthreads();
    const float4* src = (const float4*)(g_wt2 + cc * 4032);
    float4* dstw = (float4*)ws;
    for (int u = tid; u < 1008; u += 256) dstw[u] = src[u];
    __syncthreads();
#pragma unroll 1
    for (int cl = 0; cl < 4; cl++) {
      const float* aptr = as_ + (cc * 4 + cl) * 100;
#pragma unroll
      for (int r = 0; r < 9; r++) {
        int dy = r / 3, dx = r - dy * 3;
        float v0 = aptr[(ty + dy) * 10 + tx + dx];
        ull v0d = dup2(v0);
        int off = (cl * 9 + r) * 112 + s * 28;
        const ull* wp = (const ull*)(ws + off);
#pragma unroll
        for (int t = 0; t < 12; t++) ffma2(ap_[t], wp[t], v0d);
        at += ws[off + 24] * v0;
      }
    }
  }

  float acc0[25];
#pragma unroll
  for (int t = 0; t < 12; t++) {
    acc0[2 * t] = lo32(ap_[t]); acc0[2 * t + 1] = hi32(ap_[t]);
  }
  acc0[24] = at;

  int p0 = (i0 + ty) * 64 + (j0 + tx);
  float m = acc0[0];
#pragma unroll
  for (int k = 1; k < 25; k++) m = fmaxf(m, acc0[k]);
  float ssum = 0.f;
#pragma unroll
  for (int k = 0; k < 25; k++) { acc0[k] = __expf(acc0[k] - m); ssum += acc0[k]; }
  float rs = 1.f / ssum;
  float* dst = g_mask + ((size_t)(b * HW + p0)) * 100 + s;
#pragma unroll
  for (int k = 0; k < 25; k++) dst[4 * k] = acc0[k] * rs;
}

// ---------------------------------------------------------------------------
// kC: 5x5 unfold + mask-weighted sum + pixel shuffle.
// s-packed FFMA2, x via scalar LDS + dup; chains split by k-parity (4 chains).
// ---------------------------------------------------------------------------
__global__ void __launch_bounds__(128, 4) kC(const float* __restrict__ x,
                                             float* __restrict__ out) {
  extern __shared__ float xs[];   // [32][6][68] = 13056 floats
  int gc0 = blockIdx.x << 5;
  int ri = blockIdx.y;
  int b = blockIdx.z;
  int tid = threadIdx.x;
  int r = tid >> 6, j = tid & 63;
  int i = (ri << 1) + r;

  const float* xb = x + ((size_t)(b * 256 + gc0)) * HW;
  for (int u = tid; u < 3072; u += 128) {
    int c = u / 96;
    int rem = u - c * 96;
    int lr = rem >> 4, m = rem & 15;
    int grow = (ri << 1) - 2 + lr;
    float4 v = make_float4(0.f, 0.f, 0.f, 0.f);
    if ((unsigned)grow < 64u)
      v = *(const float4*)(xb + (size_t)c * HW + (grow << 6) + m * 4);
    float* d = xs + c * 408 + lr * 68 + 2 + m * 4;
    *(float2*)d = make_float2(v.x, v.y);
    *(float2*)(d + 2) = make_float2(v.z, v.w);
  }
  for (int u = tid; u < 384; u += 128) {
    int c = u / 12;
    int rem = u - c * 12;
    int lr = rem >> 1, side = rem & 1;
    *(float2*)(xs + c * 408 + lr * 68 + side * 66) = make_float2(0.f, 0.f);
  }
  __syncthreads();

  ull mk01[25], mk23[25];
  const ulonglong2* mp =
      (const ulonglong2*)(g_mask + ((size_t)(b * HW + (i << 6) + j)) * 100);
#pragma unroll
  for (int k = 0; k < 25; k++) {
    ulonglong2 v = mp[k];
    mk01[k] = v.x;
    mk23[k] = v.y;
  }

  float* ob = out + ((size_t)(b * 256 + gc0) * 128 + (i << 1)) * 128 + (j << 1);

#pragma unroll 1
  for (int c = 0; c < 32; c++) {
    const float* pq = xs + c * 408 + r * 68 + j;
    ull a01[2] = {0ull, 0ull}, a23[2] = {0ull, 0ull};
#pragma unroll
    for (int dy = 0; dy < 5; dy++) {
#pragma unroll
      for (int dx = 0; dx < 5; dx++) {
        ull pvv = dup2(pq[dy * 68 + dx]);
        int k = dy * 5 + dx;
        ffma2(a01[k & 1], mk01[k], pvv);
        ffma2(a23[k & 1], mk23[k], pvv);
      }
    }
    ull acc01 = addf32x2(a01[0], a01[1]);
    ull acc23 = addf32x2(a23[0], a23[1]);
    float* op = ob + (size_t)c * 128 * 128;
    *(float2*)op = make_float2(lo32(acc01), hi32(acc01));
    *(float2*)(op + 128) = make_float2(lo32(acc23), hi32(acc23));
  }
}

// ---------------------------------------------------------------------------
extern "C" void kernel_launch(void* const* d_in, const int* in_sizes, int n_in,
                              void* d_out, int out_size) {
  const float* x   = (const float*)d_in[0];
  const float* wc  = (const float*)d_in[1];
  const float* gma = (const float*)d_in[2];
  const float* bet = (const float*)d_in[3];
  const float* mea = (const float*)d_in[4];
  const float* var = (const float*)d_in[5];
  const float* we  = (const float*)d_in[6];
  float* out = (float*)d_out;

  int smC = 32 * 408 * 4;  // 52224
  cudaFuncSetAttribute(kC, cudaFuncAttributeMaxDynamicSharedMemorySize, smC);

  kW<<<(576 * 112 + 256 * 64 + 255) / 256, 256>>>(wc, we);
  kA<<<256, 256>>>(x, gma, bet, mea, var);
  kB<<<dim3(8, 8, 4), 256>>>();
  kC<<<dim3(8, 32, 4), 128, smC>>>(x, out);
}

// round 14
// speedup vs baseline: 1.2843x; 1.2843x over previous
#include <cuda_runtime.h>

#define HW 4096  // 64*64
typedef unsigned long long ull;

// Device scratch
__device__ float g_act[4 * 64 * HW];      // [b][co=64][h][w]
__device__ float g_mask[4 * HW * 100];    // [b][pixel][k=25][s=4]: raw logits (kB), read by kC
__device__ float g_wt2[576 * 112];        // enc w: [t=ci*9+r][s=4][28pad]
__device__ float g_wct[256 * 64];         // comp w: [c][o]

// ---- f32x2 helpers -------------------------------------------------------
__device__ __forceinline__ void ffma2(ull& d, ull a, ull b) {
  asm("fma.rn.f32x2 %0, %1, %2, %0;" : "+l"(d) : "l"(a), "l"(b));
}
__device__ __forceinline__ ull addf32x2(ull a, ull b) {
  ull d;
  asm("add.rn.f32x2 %0, %1, %2;" : "=l"(d) : "l"(a), "l"(b));
  return d;
}
__device__ __forceinline__ ull mulf32x2(ull a, ull b) {
  ull d;
  asm("mul.rn.f32x2 %0, %1, %2;" : "=l"(d) : "l"(a), "l"(b));
  return d;
}
__device__ __forceinline__ ull dup2(float v) {
  ull d;
  asm("mov.b64 %0, {%1, %1};" : "=l"(d) : "r"(__float_as_uint(v)));
  return d;
}
__device__ __forceinline__ ull pack2(float a, float b) {
  ull d;
  asm("mov.b64 %0, {%1, %2};" : "=l"(d) : "r"(__float_as_uint(a)), "r"(__float_as_uint(b)));
  return d;
}
__device__ __forceinline__ float lo32(ull d) { return __uint_as_float((unsigned)d); }
__device__ __forceinline__ float hi32(ull d) { return __uint_as_float((unsigned)(d >> 32)); }

// ---------------------------------------------------------------------------
// kW: one-time weight reorganization
// ---------------------------------------------------------------------------
__global__ void __launch_bounds__(256) kW(const float* __restrict__ wc,
                                          const float* __restrict__ we) {
  int idx = blockIdx.x * 256 + threadIdx.x;
  if (idx < 576 * 112) {
    int t = idx / 112;
    int rem = idx - t * 112;
    int s = rem / 28, k = rem - s * 28;
    g_wt2[idx] = (k < 25) ? we[(k * 4 + s) * 576 + t] : 0.f;
  }
  int j = idx - 576 * 112;
  if (j >= 0 && j < 256 * 64) {
    int c = j >> 6, o = j & 63;
    g_wct[j] = wc[o * 256 + c];
  }
}

// ---------------------------------------------------------------------------
// kA: 1x1 conv (256->64) + BN + SiLU (R9 form: 128 thr, 4 o-pairs x 4 px)
// ---------------------------------------------------------------------------
__global__ void __launch_bounds__(128) kA(
    const float* __restrict__ x,
    const float* __restrict__ gma, const float* __restrict__ bet,
    const float* __restrict__ mea, const float* __restrict__ var) {
  __shared__ float xs[64 * 64];
  __shared__ float ws[64 * 64];

  int blk = blockIdx.x;
  int b = blk >> 6;
  int p0 = (blk & 63) << 6;
  int tid = threadIdx.x;
  int pp = tid & 15;   // 4 pixels
  int po = tid >> 4;   // 8 outputs (4 pairs)

  ull acc[4][4];
#pragma unroll
  for (int a = 0; a < 4; a++)
#pragma unroll
    for (int p = 0; p < 4; p++) acc[a][p] = 0ull;

  const float* xb = x + (size_t)(b * 256) * HW + p0;

#pragma unroll 1
  for (int cc = 0; cc < 4; cc++) {
    __syncthreads();
    const float4* xg = (const float4*)(xb + (size_t)cc * 64 * HW);
    float4* xsd = (float4*)xs;
    for (int u = tid; u < 1024; u += 128) {
      int ci = u >> 4, m = u & 15;
      xsd[u] = xg[ci * 1024 + m];
    }
    const float4* wg = (const float4*)(g_wct + cc * 64 * 64);
    float4* wsd = (float4*)ws;
    for (int u = tid; u < 1024; u += 128) wsd[u] = wg[u];
    __syncthreads();

#pragma unroll 4
    for (int ci = 0; ci < 64; ci++) {
      float4 xv = *(const float4*)(xs + ci * 64 + pp * 4);
      ull xd[4] = {dup2(xv.x), dup2(xv.y), dup2(xv.z), dup2(xv.w)};
      const ull* wp = (const ull*)(ws + ci * 64 + po * 8);
#pragma unroll
      for (int op = 0; op < 4; op++) {
        ull w2 = wp[op];
#pragma unroll
        for (int p = 0; p < 4; p++) ffma2(acc[op][p], w2, xd[p]);
      }
    }
  }

  float* actb = g_act + (size_t)(b * 64) * HW + p0 + pp * 4;
#pragma unroll
  for (int op = 0; op < 4; op++) {
    int o = po * 8 + op * 2;
    float inv0 = gma[o] * rsqrtf(var[o] + 1e-5f);
    float off0 = bet[o] - mea[o] * inv0;
    float inv1 = gma[o + 1] * rsqrtf(var[o + 1] + 1e-5f);
    float off1 = bet[o + 1] - mea[o + 1] * inv1;
    float4 r0, r1;
    float v;
    v = lo32(acc[op][0]) * inv0 + off0; r0.x = v / (1.f + __expf(-v));
    v = lo32(acc[op][1]) * inv0 + off0; r0.y = v / (1.f + __expf(-v));
    v = lo32(acc[op][2]) * inv0 + off0; r0.z = v / (1.f + __expf(-v));
    v = lo32(acc[op][3]) * inv0 + off0; r0.w = v / (1.f + __expf(-v));
    v = hi32(acc[op][0]) * inv1 + off1; r1.x = v / (1.f + __expf(-v));
    v = hi32(acc[op][1]) * inv1 + off1; r1.y = v / (1.f + __expf(-v));
    v = hi32(acc[op][2]) * inv1 + off1; r1.z = v / (1.f + __expf(-v));
    v = hi32(acc[op][3]) * inv1 + off1; r1.w = v / (1.f + __expf(-v));
    *(float4*)(actb + (size_t)o * HW) = r0;
    *(float4*)(actb + (size_t)(o + 1) * HW) = r1;
  }
}

// ---------------------------------------------------------------------------
// kB: 3x3 conv (64->100ch), NO softmax, k-dimension split 2-way across blocks.
// grid (8,8,8): z = b*2 + khalf. Each block: 14-wide k-half (7 FFMA2 pairs).
// 128 threads = 32 px-slots x 4 s, 2 px/thread (weight reuse preserved).
// Writes raw logits to g_mask [pixel][k][s].
// ---------------------------------------------------------------------------
__global__ void __launch_bounds__(128, 6) kB() {
  __shared__ float as_[6400];   // act tile [64][10][10]
  __shared__ float ws[2016];    // weight half-chunk [36][s:4][14]

  int bz = blockIdx.z;
  int b = bz >> 1, kh = bz & 1;
  int i0 = blockIdx.y << 3, j0 = blockIdx.x << 3;
  int tid = threadIdx.x;
  int s = tid & 3, q = tid >> 2;
  int ty = q >> 3, tx = q & 7;

  for (int idx = tid; idx < 6400; idx += 128) {
    int ci = idx / 100;
    int rem = idx - ci * 100;
    int rr = rem / 10, cc2 = rem - rr * 10;
    int gi = i0 + rr - 1, gj = j0 + cc2 - 1;
    float v = 0.f;
    if ((unsigned)gi < 64u && (unsigned)gj < 64u)
      v = g_act[((size_t)(b * 64 + ci)) * HW + (gi << 6) + gj];
    as_[idx] = v;
  }

  ull acc0[7], acc1[7];
#pragma unroll
  for (int t = 0; t < 7; t++) { acc0[t] = 0ull; acc1[t] = 0ull; }

#pragma unroll 1
  for (int cc = 0; cc < 16; cc++) {
    __syncthreads();
    // stage weight half: ws[t][s2][14] <- g_wt2[(cc*36+t)][s2*28 + kh*14 ..+14)
    const float2* src2 = (const float2*)g_wt2;
    float2* dst2 = (float2*)ws;
    for (int u = tid; u < 1008; u += 128) {
      int t = u / 28;
      int rem = u - t * 28;
      int s2 = rem / 7, qq = rem - s2 * 7;
      dst2[u] = src2[(cc * 36 + t) * 56 + s2 * 14 + kh * 7 + qq];
    }
    __syncthreads();
#pragma unroll 1
    for (int cl = 0; cl < 4; cl++) {
      const float* ap = as_ + (cc * 4 + cl) * 100;
#pragma unroll
      for (int r = 0; r < 9; r++) {
        int dy = r / 3, dx = r - dy * 3;
        float v0 = ap[(ty + dy) * 10 + tx + dx];
        float v1 = ap[(ty + 4 + dy) * 10 + tx + dx];
        ull v0d = dup2(v0), v1d = dup2(v1);
        const ull* wp = (const ull*)(ws + (cl * 9 + r) * 56 + s * 14);
#pragma unroll
        for (int t = 0; t < 7; t++) {
          ull w2 = wp[t];
          ffma2(acc0[t], w2, v0d);
          ffma2(acc1[t], w2, v1d);
        }
      }
    }
  }

  int p0 = (i0 + ty) * 64 + (j0 + tx);
  int p1 = p0 + 256;
  float* d0 = g_mask + ((size_t)(b * HW + p0)) * 100 + s;
  float* d1 = g_mask + ((size_t)(b * HW + p1)) * 100 + s;
#pragma unroll
  for (int t = 0; t < 7; t++) {
    int k0 = kh * 14 + 2 * t;
    if (k0 < 25) { d0[4 * k0] = lo32(acc0[t]); d1[4 * k0] = lo32(acc1[t]); }
    int k1 = k0 + 1;
    if (k1 < 25) { d0[4 * k1] = hi32(acc0[t]); d1[4 * k1] = hi32(acc1[t]); }
  }
}

// ---------------------------------------------------------------------------
// kC: per-thread softmax over k (fused from kB) + 5x5 reassembly + shuffle.
// ---------------------------------------------------------------------------
__global__ void __launch_bounds__(128, 4) kC(const float* __restrict__ x,
                                             float* __restrict__ out) {
  extern __shared__ float xs[];   // [32][6][68] = 13056 floats
  int gc0 = blockIdx.x << 5;
  int ri = blockIdx.y;
  int b = blockIdx.z;
  int tid = threadIdx.x;
  int r = tid >> 6, j = tid & 63;
  int i = (ri << 1) + r;

  const float* xb = x + ((size_t)(b * 256 + gc0)) * HW;
  for (int u = tid; u < 3072; u += 128) {
    int c = u / 96;
    int rem = u - c * 96;
    int lr = rem >> 4, m = rem & 15;
    int grow = (ri << 1) - 2 + lr;
    float4 v = make_float4(0.f, 0.f, 0.f, 0.f);
    if ((unsigned)grow < 64u)
      v = *(const float4*)(xb + (size_t)c * HW + (grow << 6) + m * 4);
    float* d = xs + c * 408 + lr * 68 + 2 + m * 4;
    *(float2*)d = make_float2(v.x, v.y);
    *(float2*)(d + 2) = make_float2(v.z, v.w);
  }
  for (int u = tid; u < 384; u += 128) {
    int c = u / 12;
    int rem = u - c * 12;
    int lr = rem >> 1, side = rem & 1;
    *(float2*)(xs + c * 408 + lr * 68 + side * 66) = make_float2(0.f, 0.f);
  }
  __syncthreads();

  // raw logits -> registers (packed (s0,s1) and (s2,s3))
  ull mk01[25], mk23[25];
  const ulonglong2* mp =
      (const ulonglong2*)(g_mask + ((size_t)(b * HW + (i << 6) + j)) * 100);
#pragma unroll
  for (int k = 0; k < 25; k++) {
    ulonglong2 v = mp[k];
    mk01[k] = v.x;
    mk23[k] = v.y;
  }

  // per-s softmax over k (lo/hi of packed pairs are free register halves)
  float m0 = -1e30f, m1 = -1e30f, m2 = -1e30f, m3 = -1e30f;
#pragma unroll
  for (int k = 0; k < 25; k++) {
    m0 = fmaxf(m0, lo32(mk01[k])); m1 = fmaxf(m1, hi32(mk01[k]));
    m2 = fmaxf(m2, lo32(mk23[k])); m3 = fmaxf(m3, hi32(mk23[k]));
  }
  float s0 = 0.f, s1 = 0.f, s2 = 0.f, s3 = 0.f;
#pragma unroll
  for (int k = 0; k < 25; k++) {
    float e0 = __expf(lo32(mk01[k]) - m0);
    float e1 = __expf(hi32(mk01[k]) - m1);
    float e2 = __expf(lo32(mk23[k]) - m2);
    float e3 = __expf(hi32(mk23[k]) - m3);
    s0 += e0; s1 += e1; s2 += e2; s3 += e3;
    mk01[k] = pack2(e0, e1);
    mk23[k] = pack2(e2, e3);
  }
  ull rs01 = pack2(1.f / s0, 1.f / s1);
  ull rs23 = pack2(1.f / s2, 1.f / s3);
#pragma unroll
  for (int k = 0; k < 25; k++) {
    mk01[k] = mulf32x2(mk01[k], rs01);
    mk23[k] = mulf32x2(mk23[k], rs23);
  }

  float* ob = out + ((size_t)(b * 256 + gc0) * 128 + (i << 1)) * 128 + (j << 1);

#pragma unroll 1
  for (int c = 0; c < 32; c++) {
    const float* pq = xs + c * 408 + r * 68 + j;
    ull a01[2] = {0ull, 0ull}, a23[2] = {0ull, 0ull};
#pragma unroll
    for (int dy = 0; dy < 5; dy++) {
#pragma unroll
      for (int dx = 0; dx < 5; dx++) {
        ull pvv = dup2(pq[dy * 68 + dx]);
        int k = dy * 5 + dx;
        ffma2(a01[k & 1], mk01[k], pvv);
        ffma2(a23[k & 1], mk23[k], pvv);
      }
    }
    ull acc01 = addf32x2(a01[0], a01[1]);
    ull acc23 = addf32x2(a23[0], a23[1]);
    float* op = ob + (size_t)c * 128 * 128;
    *(float2*)op = make_float2(lo32(acc01), hi32(acc01));
    *(float2*)(op + 128) = make_float2(lo32(acc23), hi32(acc23));
  }
}

// ---------------------------------------------------------------------------
extern "C" void kernel_launch(void* const* d_in, const int* in_sizes, int n_in,
                              void* d_out, int out_size) {
  const float* x   = (const float*)d_in[0];
  const float* wc  = (const float*)d_in[1];
  const float* gma = (const float*)d_in[2];
  const float* bet = (const float*)d_in[3];
  const float* mea = (const float*)d_in[4];
  const float* var = (const float*)d_in[5];
  const float* we  = (const float*)d_in[6];
  float* out = (float*)d_out;

  int smC = 32 * 408 * 4;  // 52224
  cudaFuncSetAttribute(kC, cudaFuncAttributeMaxDynamicSharedMemorySize, smC);

  kW<<<(576 * 112 + 256 * 64 + 255) / 256, 256>>>(wc, we);
  kA<<<256, 128>>>(x, gma, bet, mea, var);
  kB<<<dim3(8, 8, 8), 128>>>();
  kC<<<dim3(8, 32, 4), 128, smC>>>(x, out);
}